// round 1
// baseline (speedup 1.0000x reference)
#include <cuda_runtime.h>

#define BB 512
#define NN 90
#define DD 1024
#define KK 45
#define THREADS 512
#define WARPS 16

__global__ __launch_bounds__(THREADS, 2)
void multig_pool_kernel(const float* __restrict__ x_sc,
                        const float* __restrict__ x_fc,
                        const float* __restrict__ pool_w,
                        const float* __restrict__ multi_w,
                        const float* __restrict__ multi_b,
                        float* __restrict__ out)
{
    __shared__ __align__(16) float spw[DD];   // pool_w staged in smem
    __shared__ float scores[NN];
    __shared__ int   sel_idx[KK];
    __shared__ float sel_w[KK];
    __shared__ float red[WARPS];
    __shared__ float s_invnorm;

    const int b    = blockIdx.x;
    const int tid  = threadIdx.x;
    const int wid  = tid >> 5;
    const int lane = tid & 31;

    // ---- Phase 0: stage pool_w, compute 1/||pool_w|| ----
    float pw2 = 0.f;
    {
        // 1024 floats / 512 threads = 2 each
        float v0 = pool_w[tid];
        float v1 = pool_w[tid + THREADS];
        spw[tid]           = v0;
        spw[tid + THREADS] = v1;
        pw2 = v0 * v0 + v1 * v1;
    }
    #pragma unroll
    for (int off = 16; off; off >>= 1) pw2 += __shfl_xor_sync(0xffffffffu, pw2, off);
    if (lane == 0) red[wid] = pw2;
    __syncthreads();
    if (tid == 0) {
        float s = 0.f;
        #pragma unroll
        for (int i = 0; i < WARPS; i++) s += red[i];
        s_invnorm = rsqrtf(s);
    }
    __syncthreads();

    const float inv_norm = s_invnorm;
    const float mw0 = multi_w[0];
    const float mw1 = multi_w[1];

    const float* __restrict__ xb_sc = x_sc + (size_t)b * NN * DD;
    const float* __restrict__ xb_fc = x_fc + (size_t)b * NN * DD;

    // ---- Phase 1: per-node dual dot-products (warp per node, strided) ----
    const float4* __restrict__ pw4 = (const float4*)spw;
    for (int n = wid; n < NN; n += WARPS) {
        const float4* rs = (const float4*)(xb_sc + (size_t)n * DD);
        const float4* rf = (const float4*)(xb_fc + (size_t)n * DD);
        float dsc = 0.f, dfc = 0.f;
        #pragma unroll
        for (int i = 0; i < 8; i++) {
            int j = lane + i * 32;
            float4 a = rs[j];
            float4 c = rf[j];
            float4 p = pw4[j];
            dsc += a.x * p.x + a.y * p.y + a.z * p.z + a.w * p.w;
            dfc += c.x * p.x + c.y * p.y + c.z * p.z + c.w * p.w;
        }
        #pragma unroll
        for (int off = 16; off; off >>= 1) {
            dsc += __shfl_xor_sync(0xffffffffu, dsc, off);
            dfc += __shfl_xor_sync(0xffffffffu, dfc, off);
        }
        if (lane == 0) {
            float t0 = tanhf(dsc * inv_norm);
            float t1 = tanhf(dfc * inv_norm);
            float z  = t0 * mw0 + t1 * mw1 + multi_b[n];
            scores[n] = 1.f / (1.f + expf(-z));
        }
    }
    __syncthreads();

    // ---- Phase 2: rank-count selection (stable descending, matches argsort(-s)) ----
    if (tid < NN) {
        float my = scores[tid];
        int rank = 0;
        #pragma unroll 10
        for (int j = 0; j < NN; j++) {
            float sj = scores[j];
            rank += (sj > my) || (sj == my && j < tid);
        }
        if (rank < KK) { sel_idx[rank] = tid; sel_w[rank] = my; }
    }
    __syncthreads();

    // ---- Phase 3: gather+scale selected rows (warp per output row) ----
    float* __restrict__ out_sc = out + (size_t)b * KK * DD;
    float* __restrict__ out_fc = out + (size_t)BB * KK * DD + (size_t)b * KK * DD;

    for (int r = wid; r < 2 * KK; r += WARPS) {
        const bool is_sc = (r < KK);
        const int  k = is_sc ? r : r - KK;
        const int  n = sel_idx[k];
        const float w = sel_w[k];
        const float4* src = (const float4*)((is_sc ? xb_sc : xb_fc) + (size_t)n * DD);
        float4* dst = (float4*)((is_sc ? out_sc : out_fc) + (size_t)k * DD);
        #pragma unroll
        for (int i = 0; i < 8; i++) {
            int j = lane + i * 32;
            float4 v = src[j];
            v.x *= w; v.y *= w; v.z *= w; v.w *= w;
            dst[j] = v;
        }
    }
}

extern "C" void kernel_launch(void* const* d_in, const int* in_sizes, int n_in,
                              void* d_out, int out_size)
{
    const float* x_sc    = (const float*)d_in[0];
    const float* x_fc    = (const float*)d_in[1];
    const float* pool_w  = (const float*)d_in[2];
    const float* multi_w = (const float*)d_in[3];
    const float* multi_b = (const float*)d_in[4];
    float* out = (float*)d_out;

    multig_pool_kernel<<<BB, THREADS>>>(x_sc, x_fc, pool_w, multi_w, multi_b, out);
}